// round 1
// baseline (speedup 1.0000x reference)
#include <cuda_runtime.h>
#include <math.h>

// Problem dims
static constexpr int Bn = 256, Sn = 20, En = 512, Hn = 512, Vn = 32000;
static constexpr int DIN1 = Sn * En + 2 * En;   // 11264
static constexpr int K1   = DIN1 + Hn;          // 11776 (x | h0 concat)
static constexpr int NG   = 4 * Hn;             // 2048 gates

// Scratch (device globals: no allocation allowed)
__device__ float g_x[Bn * K1];     // [enc_flat | word_emb | speaker_emb | h0]
__device__ float g_z[Bn * NG];     // gate pre-activations
__device__ float g_hA[Bn * Hn], g_cA[Bn * Hn];
__device__ float g_hB[Bn * Hn], g_cB[Bn * Hn];

// ---------------------------------------------------------------------------
// Build the concatenated input row: [enc(10240) | we(512) | pe[spk](512) | h0(512)]
// ---------------------------------------------------------------------------
__global__ void build_x(const float* __restrict__ enc, const float* __restrict__ we,
                        const float* __restrict__ h0, const int* __restrict__ spk,
                        const float* __restrict__ pe) {
    int idx = blockIdx.x * blockDim.x + threadIdx.x;
    if (idx >= Bn * K1) return;
    int b = idx / K1;
    int k = idx - b * K1;
    float v;
    if (k < Sn * En) {
        v = enc[b * Sn * En + k];
    } else if (k < Sn * En + En) {
        v = we[b * En + (k - Sn * En)];
    } else if (k < DIN1) {
        v = pe[spk[b] * En + (k - Sn * En - En)];
    } else {
        v = h0[b * Hn + (k - DIN1)];
    }
    g_x[idx] = v;
}

// ---------------------------------------------------------------------------
// Tiled SGEMM: C(MxN) = A(MxK) @ B(KxN) + bias, fp32.
// MODE 0: B = B0
// MODE 1: B rows < Ksplit from B0, rows >= Ksplit from B1 (row k-Ksplit)
// MODE 2: B = B0 + B1 elementwise
// Requires M%64==0, N%64==0, K%16==0, Ksplit%16==0.
// 64x64 tile, BK=16, 256 threads, 4x4 microtile, float4 fragments.
// ---------------------------------------------------------------------------
template <int MODE>
__global__ __launch_bounds__(256)
void gemm64(const float* __restrict__ A, const float* __restrict__ B0,
            const float* __restrict__ B1, const float* __restrict__ bias,
            float* __restrict__ C, int M, int N, int K, int Ksplit) {
    __shared__ __align__(16) float As[16][64];  // [k][m]
    __shared__ __align__(16) float Bs[16][64];  // [k][n]

    const int m0 = blockIdx.y * 64;
    const int n0 = blockIdx.x * 64;
    const int tid = threadIdx.x;
    const int ty = tid >> 4;          // 0..15  (m groups of 4)
    const int tx = tid & 15;          // 0..15  (n groups of 4)

    float acc[4][4];
#pragma unroll
    for (int i = 0; i < 4; i++)
#pragma unroll
        for (int j = 0; j < 4; j++) acc[i][j] = 0.f;

    // A-tile loader mapping: each thread loads one float4 of a row
    const int ar = tid >> 2;                // 0..63 row within tile
    const int akq = (tid & 3) * 4;          // 0,4,8,12 col quad
    // B-tile loader mapping
    const int bkr = tid >> 4;               // 0..15 row within tile
    const int bcq = (tid & 15) * 4;         // col quad

    for (int k0 = 0; k0 < K; k0 += 16) {
        // Load A tile (transposed into SMEM: As[k][m])
        {
            float4 av = *(const float4*)&A[(size_t)(m0 + ar) * K + k0 + akq];
            As[akq + 0][ar] = av.x;
            As[akq + 1][ar] = av.y;
            As[akq + 2][ar] = av.z;
            As[akq + 3][ar] = av.w;
        }
        // Load B tile
        {
            int gk = k0 + bkr;
            float4 bv;
            if (MODE == 0) {
                bv = *(const float4*)&B0[(size_t)gk * N + n0 + bcq];
            } else if (MODE == 1) {
                if (gk < Ksplit)
                    bv = *(const float4*)&B0[(size_t)gk * N + n0 + bcq];
                else
                    bv = *(const float4*)&B1[(size_t)(gk - Ksplit) * N + n0 + bcq];
            } else {
                float4 b0v = *(const float4*)&B0[(size_t)gk * N + n0 + bcq];
                float4 b1v = *(const float4*)&B1[(size_t)gk * N + n0 + bcq];
                bv = make_float4(b0v.x + b1v.x, b0v.y + b1v.y,
                                 b0v.z + b1v.z, b0v.w + b1v.w);
            }
            *(float4*)&Bs[bkr][bcq] = bv;
        }
        __syncthreads();

#pragma unroll
        for (int kk = 0; kk < 16; kk++) {
            float4 a = *(const float4*)&As[kk][ty * 4];
            float4 bq = *(const float4*)&Bs[kk][tx * 4];
            acc[0][0] += a.x * bq.x; acc[0][1] += a.x * bq.y;
            acc[0][2] += a.x * bq.z; acc[0][3] += a.x * bq.w;
            acc[1][0] += a.y * bq.x; acc[1][1] += a.y * bq.y;
            acc[1][2] += a.y * bq.z; acc[1][3] += a.y * bq.w;
            acc[2][0] += a.z * bq.x; acc[2][1] += a.z * bq.y;
            acc[2][2] += a.z * bq.z; acc[2][3] += a.z * bq.w;
            acc[3][0] += a.w * bq.x; acc[3][1] += a.w * bq.y;
            acc[3][2] += a.w * bq.z; acc[3][3] += a.w * bq.w;
        }
        __syncthreads();
    }

    const int col = n0 + tx * 4;
    float4 bb = *(const float4*)&bias[col];
#pragma unroll
    for (int i = 0; i < 4; i++) {
        int row = m0 + ty * 4 + i;
        float4 o = make_float4(acc[i][0] + bb.x, acc[i][1] + bb.y,
                               acc[i][2] + bb.z, acc[i][3] + bb.w);
        *(float4*)&C[(size_t)row * N + col] = o;
    }
}

// ---------------------------------------------------------------------------
// LSTM gate nonlinearity (Keras order i,f,g,o; activation=relu)
// ---------------------------------------------------------------------------
__device__ __forceinline__ float sigmoidf(float x) { return 1.f / (1.f + expf(-x)); }

__global__ void lstm_gate(const float* __restrict__ z, const float* __restrict__ c_prev,
                          float* __restrict__ h_out, float* __restrict__ c_out) {
    int idx = blockIdx.x * blockDim.x + threadIdx.x;
    if (idx >= Bn * Hn) return;
    int b = idx / Hn;
    int j = idx - b * Hn;
    const float* zr = z + (size_t)b * NG;
    float ig = sigmoidf(zr[j]);
    float fg = sigmoidf(zr[Hn + j]);
    float gg = fmaxf(zr[2 * Hn + j], 0.f);
    float og = sigmoidf(zr[3 * Hn + j]);
    float cn = fg * c_prev[idx] + ig * gg;
    c_out[idx] = cn;
    h_out[idx] = og * fmaxf(cn, 0.f);
}

// ---------------------------------------------------------------------------
// Softmax in place on (Bn x Vn), one block per row.
// ---------------------------------------------------------------------------
__global__ __launch_bounds__(512)
void softmax_inplace(float* __restrict__ probs) {
    const int b = blockIdx.x;
    float* row = probs + (size_t)b * Vn;
    const int tid = threadIdx.x;
    const int nt = blockDim.x;
    __shared__ float sred[33];

    // pass 1: max
    float m = -3.4e38f;
    for (int i = tid; i < Vn; i += nt) m = fmaxf(m, row[i]);
#pragma unroll
    for (int o = 16; o > 0; o >>= 1) m = fmaxf(m, __shfl_xor_sync(0xffffffffu, m, o));
    if ((tid & 31) == 0) sred[tid >> 5] = m;
    __syncthreads();
    if (tid == 0) {
        float v = sred[0];
        for (int w = 1; w < nt / 32; w++) v = fmaxf(v, sred[w]);
        sred[32] = v;
    }
    __syncthreads();
    m = sred[32];

    // pass 2: exp + sum
    float s = 0.f;
    for (int i = tid; i < Vn; i += nt) {
        float e = expf(row[i] - m);
        row[i] = e;
        s += e;
    }
    __syncthreads();  // everyone done reading sred[32]
#pragma unroll
    for (int o = 16; o > 0; o >>= 1) s += __shfl_xor_sync(0xffffffffu, s, o);
    if ((tid & 31) == 0) sred[tid >> 5] = s;
    __syncthreads();
    if (tid == 0) {
        float v = 0.f;
        for (int w = 0; w < nt / 32; w++) v += sred[w];
        sred[32] = v;
    }
    __syncthreads();
    float inv = 1.f / sred[32];

    // pass 3: normalize
    for (int i = tid; i < Vn; i += nt) row[i] *= inv;
}

// Append h4, c4 after probs in the output buffer.
__global__ void copy_tail(const float* __restrict__ h4, const float* __restrict__ c4,
                          float* __restrict__ out) {
    int i = blockIdx.x * blockDim.x + threadIdx.x;
    if (i >= Bn * Hn) return;
    out[(size_t)Bn * Vn + i] = h4[i];
    out[(size_t)Bn * Vn + (size_t)Bn * Hn + i] = c4[i];
}

// ---------------------------------------------------------------------------
// Launch
// ---------------------------------------------------------------------------
extern "C" void kernel_launch(void* const* d_in, const int* in_sizes, int n_in,
                              void* d_out, int out_size) {
    const float* enc = (const float*)d_in[0];
    const float* we  = (const float*)d_in[1];
    const float* h0  = (const float*)d_in[2];
    const float* c0  = (const float*)d_in[3];
    const int*   spk = (const int*)d_in[4];
    // d_in[5] = addressee (unused in the is_speaker branch)
    const float* pe  = (const float*)d_in[6];
    const float* W1 = (const float*)d_in[7];
    const float* U1 = (const float*)d_in[8];
    const float* b1 = (const float*)d_in[9];
    const float* W2 = (const float*)d_in[10];
    const float* U2 = (const float*)d_in[11];
    const float* b2 = (const float*)d_in[12];
    const float* W3 = (const float*)d_in[13];
    const float* U3 = (const float*)d_in[14];
    const float* b3 = (const float*)d_in[15];
    const float* W4 = (const float*)d_in[16];
    const float* U4 = (const float*)d_in[17];
    const float* b4 = (const float*)d_in[18];
    const float* Wd = (const float*)d_in[19];
    const float* bd = (const float*)d_in[20];
    float* out = (float*)d_out;

    // Resolve scratch symbol addresses (no allocation; capture-safe API)
    float *xp, *zp, *hA, *cA, *hB, *cB;
    cudaGetSymbolAddress((void**)&xp, g_x);
    cudaGetSymbolAddress((void**)&zp, g_z);
    cudaGetSymbolAddress((void**)&hA, g_hA);
    cudaGetSymbolAddress((void**)&cA, g_cA);
    cudaGetSymbolAddress((void**)&hB, g_hB);
    cudaGetSymbolAddress((void**)&cB, g_cB);

    // 1. Build concatenated input
    build_x<<<(Bn * K1 + 255) / 256, 256>>>(enc, we, h0, spk, pe);

    // 2. Layer 1: z = x @ [W1;U1] + b1  (K split at 11264), then gates
    gemm64<1><<<dim3(NG / 64, Bn / 64), 256>>>(xp, W1, U1, b1, zp, Bn, NG, K1, DIN1);
    lstm_gate<<<(Bn * Hn + 255) / 256, 256>>>(zp, c0, hA, cA);

    // 3. Layers 2-4: z = h @ (W + U) + b  (x == h in the reference)
    gemm64<2><<<dim3(NG / 64, Bn / 64), 256>>>(hA, W2, U2, b2, zp, Bn, NG, Hn, 0);
    lstm_gate<<<(Bn * Hn + 255) / 256, 256>>>(zp, cA, hB, cB);

    gemm64<2><<<dim3(NG / 64, Bn / 64), 256>>>(hB, W3, U3, b3, zp, Bn, NG, Hn, 0);
    lstm_gate<<<(Bn * Hn + 255) / 256, 256>>>(zp, cB, hA, cA);

    gemm64<2><<<dim3(NG / 64, Bn / 64), 256>>>(hA, W4, U4, b4, zp, Bn, NG, Hn, 0);
    lstm_gate<<<(Bn * Hn + 255) / 256, 256>>>(zp, cA, hB, cB);
    // final h4 = hB, c4 = cB

    // 4. Decode: logits into d_out, softmax in place
    gemm64<0><<<dim3(Vn / 64, Bn / 64), 256>>>(hB, Wd, nullptr, bd, out, Bn, Vn, Hn, 0);
    softmax_inplace<<<Bn, 512>>>(out);

    // 5. Append h4, c4 if the output buffer carries them
    if (out_size >= Bn * Vn + 2 * Bn * Hn) {
        copy_tail<<<(Bn * Hn + 255) / 256, 256>>>(hB, cB, out);
    }
}

// round 3
// speedup vs baseline: 2.1414x; 2.1414x over previous
#include <cuda_runtime.h>
#include <mma.h>
#include <math.h>
#include <cstdint>

using namespace nvcuda;

// Problem dims
static constexpr int Bn = 256, Sn = 20, En = 512, Hn = 512, Vn = 32000;
static constexpr int DIN1 = Sn * En + 2 * En;   // 11264
static constexpr int K1   = DIN1 + Hn;          // 11776 ([x | h0] concat)
static constexpr int NG   = 4 * Hn;             // 2048 gates

// Scratch (device globals; allocation is forbidden)
__device__ float g_x[Bn * K1];          // [enc_flat | we | spk_emb | h0]
__device__ float g_part[8 * Bn * NG];   // split-K partials (max KS=8)
__device__ float g_hdup[Bn * 2 * Hn];   // [h | h] for layers 2-4
__device__ float g_h4[Bn * Hn];
__device__ float g_c[Bn * Hn];

// ---------------------------------------------------------------------------
// Build concatenated input row: [enc(10240) | we(512) | pe[spk](512) | h0(512)]
// ---------------------------------------------------------------------------
__global__ void build_x(const float* __restrict__ enc, const float* __restrict__ we,
                        const float* __restrict__ h0, const int* __restrict__ spk,
                        const float* __restrict__ pe) {
    int idx = blockIdx.x * blockDim.x + threadIdx.x;
    if (idx >= Bn * K1) return;
    int b = idx / K1;
    int k = idx - b * K1;
    float v;
    if (k < Sn * En)            v = enc[b * Sn * En + k];
    else if (k < Sn * En + En)  v = we[b * En + (k - Sn * En)];
    else if (k < DIN1)          v = pe[spk[b] * En + (k - Sn * En - En)];
    else                        v = h0[b * Hn + (k - DIN1)];
    g_x[idx] = v;
}

// ---------------------------------------------------------------------------
// tf32 tensor-core GEMM.  C_partial(MxN) = A(MxK) @ B(KxN), no bias.
// MODE 0: B = B0.  MODE 1: B row gk < Ksplit from B0, else B1[gk-Ksplit].
// Block tile 128x64, BK=32, 256 threads (8 warps, 4x2), warp tile 32x32.
// grid = (N/64, M/128, KS); block z = ks handles k in [ks*Kchunk, (ks+1)*Kchunk).
// Output written to Cout + ks*M*N  (KS==1 -> direct output).
// Dynamic smem: 2 stages, As[128][36], Bs[32][68].
// ---------------------------------------------------------------------------
#define CP_ASYNC16(dst, src) \
    asm volatile("cp.async.cg.shared.global [%0], [%1], 16;\n" :: "r"(dst), "l"(src))

static constexpr int AS_LD = 36;   // 128 rows of 32 + pad4 (stride 144B, 16B-mult)
static constexpr int BS_LD = 68;   // 32 rows of 64 + pad4 (stride 272B, 16B-mult)
static constexpr int AS_ELEMS = 128 * AS_LD;
static constexpr int BS_ELEMS = 32 * BS_LD;
static constexpr int GEMM_SMEM_BYTES = (2 * AS_ELEMS + 2 * BS_ELEMS) * 4;  // 54272

template <int MODE>
__global__ __launch_bounds__(256)
void gemm_tc(const float* __restrict__ A, const float* __restrict__ B0,
             const float* __restrict__ B1, float* __restrict__ Cout,
             int M, int N, int K, int Ksplit, int Kchunk) {
    extern __shared__ float smem[];
    float* AsBase = smem;                       // [2][128][AS_LD]
    float* BsBase = smem + 2 * AS_ELEMS;        // [2][32][BS_LD]

    const int n0 = blockIdx.x * 64;
    const int m0 = blockIdx.y * 128;
    const int ks = blockIdx.z;
    const int kbase = ks * Kchunk;
    const int iters = Kchunk / 32;
    const int tid = threadIdx.x;

    // A loader: thread -> row tid>>1, col base (tid&1)*16, 4 float4
    const int a_row = tid >> 1;
    const int a_col = (tid & 1) * 16;
    // B loader: thread -> row tid>>3, col base (tid&7)*8, 2 float4
    const int b_row = tid >> 3;
    const int b_col = (tid & 7) * 8;

    const int wid = tid >> 5;
    const int wm = wid >> 1;   // 0..3
    const int wn = wid & 1;    // 0..1

    wmma::fragment<wmma::accumulator, 16, 16, 8, float> acc[2][2];
#pragma unroll
    for (int i = 0; i < 2; i++)
#pragma unroll
        for (int j = 0; j < 2; j++) wmma::fill_fragment(acc[i][j], 0.f);

    auto load_stage = [&](int s, int k0) {
        // A tile: 128 x 32
        {
            const float* ag = A + (size_t)(m0 + a_row) * K + k0 + a_col;
            unsigned as = (unsigned)__cvta_generic_to_shared(
                AsBase + s * AS_ELEMS + a_row * AS_LD + a_col);
#pragma unroll
            for (int j = 0; j < 4; j++) CP_ASYNC16(as + j * 16, ag + j * 4);
        }
        // B tile: 32 x 64
        {
            int gk = k0 + b_row;
            const float* brow;
            if (MODE == 1 && gk >= Ksplit)
                brow = B1 + (size_t)(gk - Ksplit) * N + n0 + b_col;
            else
                brow = B0 + (size_t)gk * N + n0 + b_col;
            unsigned bs = (unsigned)__cvta_generic_to_shared(
                BsBase + s * BS_ELEMS + b_row * BS_LD + b_col);
#pragma unroll
            for (int j = 0; j < 2; j++) CP_ASYNC16(bs + j * 16, brow + j * 4);
        }
        asm volatile("cp.async.commit_group;\n");
    };

    load_stage(0, kbase);

    for (int it = 0; it < iters; ++it) {
        const int s = it & 1;
        if (it + 1 < iters) {
            load_stage(s ^ 1, kbase + (it + 1) * 32);
            asm volatile("cp.async.wait_group 1;\n");
        } else {
            asm volatile("cp.async.wait_group 0;\n");
        }
        __syncthreads();

        const float* As = AsBase + s * AS_ELEMS;
        const float* Bs = BsBase + s * BS_ELEMS;
#pragma unroll
        for (int kk = 0; kk < 4; ++kk) {
            wmma::fragment<wmma::matrix_a, 16, 16, 8, wmma::precision::tf32,
                           wmma::row_major> af[2];
            wmma::fragment<wmma::matrix_b, 16, 16, 8, wmma::precision::tf32,
                           wmma::row_major> bf[2];
#pragma unroll
            for (int i = 0; i < 2; i++) {
                wmma::load_matrix_sync(af[i], As + (wm * 32 + i * 16) * AS_LD + kk * 8,
                                       AS_LD);
#pragma unroll
                for (int e = 0; e < af[i].num_elements; e++)
                    af[i].x[e] = wmma::__float_to_tf32(af[i].x[e]);
            }
#pragma unroll
            for (int j = 0; j < 2; j++) {
                wmma::load_matrix_sync(bf[j], Bs + (kk * 8) * BS_LD + wn * 32 + j * 16,
                                       BS_LD);
#pragma unroll
                for (int e = 0; e < bf[j].num_elements; e++)
                    bf[j].x[e] = wmma::__float_to_tf32(bf[j].x[e]);
            }
#pragma unroll
            for (int i = 0; i < 2; i++)
#pragma unroll
                for (int j = 0; j < 2; j++)
                    wmma::mma_sync(acc[i][j], af[i], bf[j], acc[i][j]);
        }
        __syncthreads();
    }

    float* C = Cout + (size_t)ks * M * N;
#pragma unroll
    for (int i = 0; i < 2; i++)
#pragma unroll
        for (int j = 0; j < 2; j++)
            wmma::store_matrix_sync(
                C + (size_t)(m0 + wm * 32 + i * 16) * N + n0 + wn * 32 + j * 16,
                acc[i][j], N, wmma::mem_row_major);
}

// ---------------------------------------------------------------------------
// Gate kernel: reduce KS split-K partials + bias, apply LSTM nonlinearity
// (Keras order i,f,g,o; activation=relu). Writes duplicated [h|h] and/or flat h.
// ---------------------------------------------------------------------------
__global__ void lstm_gate_tc(const float* __restrict__ P, int KS,
                             const float* __restrict__ c_prev,
                             float* __restrict__ c_out,
                             const float* __restrict__ bias,
                             float* __restrict__ hdup, float* __restrict__ hflat) {
    int idx = blockIdx.x * blockDim.x + threadIdx.x;
    if (idx >= Bn * Hn) return;
    int b = idx / Hn;
    int j = idx - b * Hn;
    float zi = bias[j], zf = bias[Hn + j], zg = bias[2 * Hn + j], zo = bias[3 * Hn + j];
    for (int ks = 0; ks < KS; ks++) {
        const float* zr = P + ((size_t)ks * Bn + b) * NG;
        zi += zr[j];
        zf += zr[Hn + j];
        zg += zr[2 * Hn + j];
        zo += zr[3 * Hn + j];
    }
    float ig = 1.f / (1.f + expf(-zi));
    float fg = 1.f / (1.f + expf(-zf));
    float gg = fmaxf(zg, 0.f);
    float og = 1.f / (1.f + expf(-zo));
    float cn = fg * c_prev[idx] + ig * gg;
    c_out[idx] = cn;
    float h = og * fmaxf(cn, 0.f);
    if (hdup) {
        hdup[(size_t)b * 2 * Hn + j] = h;
        hdup[(size_t)b * 2 * Hn + Hn + j] = h;
    }
    if (hflat) hflat[idx] = h;
}

// ---------------------------------------------------------------------------
// Softmax in place on (Bn x Vn), one block per row; adds bias bd to the logits.
// ---------------------------------------------------------------------------
__global__ __launch_bounds__(512)
void softmax_bias(float* __restrict__ probs, const float* __restrict__ bd) {
    const int b = blockIdx.x;
    float* row = probs + (size_t)b * Vn;
    const int tid = threadIdx.x;
    const int nt = blockDim.x;
    __shared__ float sred[33];

    float m = -3.4e38f;
    for (int i = tid; i < Vn; i += nt) m = fmaxf(m, row[i] + bd[i]);
#pragma unroll
    for (int o = 16; o > 0; o >>= 1) m = fmaxf(m, __shfl_xor_sync(0xffffffffu, m, o));
    if ((tid & 31) == 0) sred[tid >> 5] = m;
    __syncthreads();
    if (tid == 0) {
        float v = sred[0];
        for (int w = 1; w < nt / 32; w++) v = fmaxf(v, sred[w]);
        sred[32] = v;
    }
    __syncthreads();
    m = sred[32];

    float s = 0.f;
    for (int i = tid; i < Vn; i += nt) {
        float e = expf(row[i] + bd[i] - m);
        row[i] = e;
        s += e;
    }
    __syncthreads();
#pragma unroll
    for (int o = 16; o > 0; o >>= 1) s += __shfl_xor_sync(0xffffffffu, s, o);
    if ((tid & 31) == 0) sred[tid >> 5] = s;
    __syncthreads();
    if (tid == 0) {
        float v = 0.f;
        for (int w = 0; w < nt / 32; w++) v += sred[w];
        sred[32] = v;
    }
    __syncthreads();
    float inv = 1.f / sred[32];
    for (int i = tid; i < Vn; i += nt) row[i] *= inv;
}

__global__ void copy_tail(const float* __restrict__ h4, const float* __restrict__ c4,
                          float* __restrict__ out) {
    int i = blockIdx.x * blockDim.x + threadIdx.x;
    if (i >= Bn * Hn) return;
    out[(size_t)Bn * Vn + i] = h4[i];
    out[(size_t)Bn * Vn + (size_t)Bn * Hn + i] = c4[i];
}

// ---------------------------------------------------------------------------
// Launch
// ---------------------------------------------------------------------------
extern "C" void kernel_launch(void* const* d_in, const int* in_sizes, int n_in,
                              void* d_out, int out_size) {
    const float* enc = (const float*)d_in[0];
    const float* we  = (const float*)d_in[1];
    const float* h0  = (const float*)d_in[2];
    const float* c0  = (const float*)d_in[3];
    const int*   spk = (const int*)d_in[4];
    // d_in[5] = addressee (unused)
    const float* pe  = (const float*)d_in[6];
    const float* W1 = (const float*)d_in[7];
    const float* U1 = (const float*)d_in[8];
    const float* b1 = (const float*)d_in[9];
    const float* W2 = (const float*)d_in[10];
    const float* U2 = (const float*)d_in[11];
    const float* b2 = (const float*)d_in[12];
    const float* W3 = (const float*)d_in[13];
    const float* U3 = (const float*)d_in[14];
    const float* b3 = (const float*)d_in[15];
    const float* W4 = (const float*)d_in[16];
    const float* U4 = (const float*)d_in[17];
    const float* b4 = (const float*)d_in[18];
    const float* Wd = (const float*)d_in[19];
    const float* bd = (const float*)d_in[20];
    float* out = (float*)d_out;

    float *xp, *pp, *hd, *h4, *cp;
    cudaGetSymbolAddress((void**)&xp, g_x);
    cudaGetSymbolAddress((void**)&pp, g_part);
    cudaGetSymbolAddress((void**)&hd, g_hdup);
    cudaGetSymbolAddress((void**)&h4, g_h4);
    cudaGetSymbolAddress((void**)&cp, g_c);

    cudaFuncSetAttribute(gemm_tc<0>, cudaFuncAttributeMaxDynamicSharedMemorySize,
                         GEMM_SMEM_BYTES);
    cudaFuncSetAttribute(gemm_tc<1>, cudaFuncAttributeMaxDynamicSharedMemorySize,
                         GEMM_SMEM_BYTES);

    // 1. Build concatenated input
    build_x<<<(Bn * K1 + 255) / 256, 256>>>(enc, we, h0, spk, pe);

    // 2. Layer 1: z = [x|h0] @ [W1;U1]  (K=11776, split at 11264, KS=8)
    gemm_tc<1><<<dim3(NG / 64, Bn / 128, 8), 256, GEMM_SMEM_BYTES>>>(
        xp, W1, U1, pp, Bn, NG, K1, DIN1, K1 / 8);
    lstm_gate_tc<<<(Bn * Hn + 255) / 256, 256>>>(pp, 8, c0, cp, b1, hd, nullptr);

    // 3. Layers 2-4: z = [h|h] @ [W;U]  (K=1024, split at 512, KS=2)
    gemm_tc<1><<<dim3(NG / 64, Bn / 128, 2), 256, GEMM_SMEM_BYTES>>>(
        hd, W2, U2, pp, Bn, NG, 2 * Hn, Hn, Hn);
    lstm_gate_tc<<<(Bn * Hn + 255) / 256, 256>>>(pp, 2, cp, cp, b2, hd, nullptr);

    gemm_tc<1><<<dim3(NG / 64, Bn / 128, 2), 256, GEMM_SMEM_BYTES>>>(
        hd, W3, U3, pp, Bn, NG, 2 * Hn, Hn, Hn);
    lstm_gate_tc<<<(Bn * Hn + 255) / 256, 256>>>(pp, 2, cp, cp, b3, hd, nullptr);

    gemm_tc<1><<<dim3(NG / 64, Bn / 128, 2), 256, GEMM_SMEM_BYTES>>>(
        hd, W4, U4, pp, Bn, NG, 2 * Hn, Hn, Hn);
    lstm_gate_tc<<<(Bn * Hn + 255) / 256, 256>>>(pp, 2, cp, cp, b4, nullptr, h4);

    // 4. Decode: logits = h4 @ Wd (bias folded into softmax), softmax in place
    gemm_tc<0><<<dim3(Vn / 64, Bn / 128, 1), 256, GEMM_SMEM_BYTES>>>(
        h4, Wd, nullptr, out, Bn, Vn, Hn, 0, Hn);
    softmax_bias<<<Bn, 512>>>(out, bd);

    // 5. Append h4, c4
    if (out_size >= Bn * Vn + 2 * Bn * Hn) {
        copy_tail<<<(Bn * Hn + 255) / 256, 256>>>(h4, cp, out);
    }
}

// round 4
// speedup vs baseline: 2.5017x; 1.1682x over previous
#include <cuda_runtime.h>
#include <cuda_bf16.h>
#include <mma.h>
#include <math.h>
#include <cstdint>

using namespace nvcuda;

// Problem dims
static constexpr int Bn = 256, Sn = 20, En = 512, Hn = 512, Vn = 32000;
static constexpr int DIN1 = Sn * En + 2 * En;   // 11264
static constexpr int K1   = DIN1 + Hn;          // 11776 ([x | h0] concat)
static constexpr int NG   = 4 * Hn;             // 2048 gates

// Scratch (device globals; allocation is forbidden)
__device__ float g_x[Bn * K1];          // [enc_flat | we | spk_emb | h0]
__device__ float g_part[8 * Bn * NG];   // split-K partials (max KS=8)
__device__ float g_hdup[Bn * 2 * Hn];   // [h | h] for layers 2-4
__device__ float g_h4[Bn * Hn];
__device__ float g_c[Bn * Hn];

// ---------------------------------------------------------------------------
// Build concatenated input row: [enc(10240) | we(512) | pe[spk](512) | h0(512)]
// ---------------------------------------------------------------------------
__global__ void build_x(const float* __restrict__ enc, const float* __restrict__ we,
                        const float* __restrict__ h0, const int* __restrict__ spk,
                        const float* __restrict__ pe) {
    int idx = blockIdx.x * blockDim.x + threadIdx.x;
    if (idx >= Bn * K1) return;
    int b = idx / K1;
    int k = idx - b * K1;
    float v;
    if (k < Sn * En)            v = enc[b * Sn * En + k];
    else if (k < Sn * En + En)  v = we[b * En + (k - Sn * En)];
    else if (k < DIN1)          v = pe[spk[b] * En + (k - Sn * En - En)];
    else                        v = h0[b * Hn + (k - DIN1)];
    g_x[idx] = v;
}

// ---------------------------------------------------------------------------
// Split-bf16 tensor-core GEMM (3-MMA error compensation; ~16-bit mantissa).
// C_partial(MxN) = A(MxK) @ B(KxN).
// MODE 0: B = B0.  MODE 1: B row gk < Ksplit from B0, else B1[gk-Ksplit].
// Block tile 128x64, BK=32, 256 threads (8 warps 4x2), warp tile 32x32.
// grid = (N/64, M/128, KS); output to Cout + ks*M*N.
// Loader: LDG f32 (double-buffered in regs) -> split hi/lo bf16 -> STS.
// One __syncthreads per K-iter (2-stage smem rotation).
// ---------------------------------------------------------------------------
static constexpr int ALD = 40;                 // halfs per A row (32 + pad 8)
static constexpr int BLD = 72;                 // halfs per B row (64 + pad 8)
static constexpr int A_HALFS = 128 * ALD;      // 5120
static constexpr int B_HALFS = 32 * BLD;       // 2304
// layout: Ah[2] Al[2] Bh[2] Bl[2]
static constexpr int GEMM_SMEM_BYTES = (4 * A_HALFS + 4 * B_HALFS) * 2;  // 59392

__device__ __forceinline__ void split4(const float4 f, __nv_bfloat16* hi,
                                       __nv_bfloat16* lo) {
    float v[4] = {f.x, f.y, f.z, f.w};
#pragma unroll
    for (int i = 0; i < 4; i++) {
        __nv_bfloat16 h = __float2bfloat16_rn(v[i]);
        hi[i] = h;
        lo[i] = __float2bfloat16_rn(v[i] - __bfloat162float(h));
    }
}

template <int MODE>
__global__ __launch_bounds__(256, 2)
void gemm_bf3(const float* __restrict__ A, const float* __restrict__ B0,
              const float* __restrict__ B1, float* __restrict__ Cout,
              int M, int N, int K, int Ksplit, int Kchunk) {
    extern __shared__ __nv_bfloat16 sm[];
    __nv_bfloat16* Ah = sm;                    // [2][A_HALFS]
    __nv_bfloat16* Al = sm + 2 * A_HALFS;
    __nv_bfloat16* Bh = sm + 4 * A_HALFS;      // [2][B_HALFS]
    __nv_bfloat16* Bl = sm + 4 * A_HALFS + 2 * B_HALFS;

    const int n0 = blockIdx.x * 64;
    const int m0 = blockIdx.y * 128;
    const int ks = blockIdx.z;
    const int kbase = ks * Kchunk;
    const int iters = Kchunk / 32;
    const int tid = threadIdx.x;

    // A loader: row = tid>>1 (0..127), col base (tid&1)*16, 4 float4
    const int a_row = tid >> 1;
    const int a_col = (tid & 1) * 16;
    // B loader: row = tid>>3 (0..31), col base (tid&7)*8, 2 float4
    const int b_row = tid >> 3;
    const int b_col = (tid & 7) * 8;

    const int wid = tid >> 5;
    const int wm = wid >> 1;   // 0..3 -> m offset wm*32
    const int wn = wid & 1;    // 0..1 -> n offset wn*32

    const float* Agp = A + (size_t)(m0 + a_row) * K + a_col + kbase;

    wmma::fragment<wmma::accumulator, 16, 16, 16, float> acc[2][2];
#pragma unroll
    for (int i = 0; i < 2; i++)
#pragma unroll
        for (int j = 0; j < 2; j++) wmma::fill_fragment(acc[i][j], 0.f);

    float4 aReg[4];
    float4 bReg[2];

    auto ldg_stage = [&](int it) {
#pragma unroll
        for (int j = 0; j < 4; j++)
            aReg[j] = *(const float4*)(Agp + it * 32 + j * 4);
        int gk = kbase + it * 32 + b_row;
        const float* brow;
        if (MODE == 1 && gk >= Ksplit)
            brow = B1 + (size_t)(gk - Ksplit) * N + n0 + b_col;
        else
            brow = B0 + (size_t)gk * N + n0 + b_col;
#pragma unroll
        for (int j = 0; j < 2; j++) bReg[j] = *(const float4*)(brow + j * 4);
    };

    auto sts_stage = [&](int s) {
        __nv_bfloat16 h4v[4], l4v[4];
#pragma unroll
        for (int j = 0; j < 4; j++) {
            split4(aReg[j], h4v, l4v);
            int off = s * A_HALFS + a_row * ALD + a_col + j * 4;
            *(uint2*)&Ah[off] = *(uint2*)h4v;
            *(uint2*)&Al[off] = *(uint2*)l4v;
        }
#pragma unroll
        for (int j = 0; j < 2; j++) {
            split4(bReg[j], h4v, l4v);
            int off = s * B_HALFS + b_row * BLD + b_col + j * 4;
            *(uint2*)&Bh[off] = *(uint2*)h4v;
            *(uint2*)&Bl[off] = *(uint2*)l4v;
        }
    };

    ldg_stage(0);

    for (int it = 0; it < iters; ++it) {
        const int s = it & 1;
        sts_stage(s);
        if (it + 1 < iters) ldg_stage(it + 1);   // LDG in flight during MMA
        __syncthreads();

        const __nv_bfloat16* ah = Ah + s * A_HALFS + (wm * 32) * ALD;
        const __nv_bfloat16* al = Al + s * A_HALFS + (wm * 32) * ALD;
        const __nv_bfloat16* bh = Bh + s * B_HALFS + wn * 32;
        const __nv_bfloat16* bl = Bl + s * B_HALFS + wn * 32;

#pragma unroll
        for (int kk = 0; kk < 2; ++kk) {
            wmma::fragment<wmma::matrix_a, 16, 16, 16, __nv_bfloat16,
                           wmma::row_major> afh[2], afl[2];
            wmma::fragment<wmma::matrix_b, 16, 16, 16, __nv_bfloat16,
                           wmma::row_major> bfh[2], bfl[2];
#pragma unroll
            for (int i = 0; i < 2; i++) {
                wmma::load_matrix_sync(afh[i], ah + i * 16 * ALD + kk * 16, ALD);
                wmma::load_matrix_sync(afl[i], al + i * 16 * ALD + kk * 16, ALD);
            }
#pragma unroll
            for (int j = 0; j < 2; j++) {
                wmma::load_matrix_sync(bfh[j], bh + kk * 16 * BLD + j * 16, BLD);
                wmma::load_matrix_sync(bfl[j], bl + kk * 16 * BLD + j * 16, BLD);
            }
#pragma unroll
            for (int i = 0; i < 2; i++)
#pragma unroll
                for (int j = 0; j < 2; j++) {
                    wmma::mma_sync(acc[i][j], afh[i], bfh[j], acc[i][j]);
                    wmma::mma_sync(acc[i][j], afh[i], bfl[j], acc[i][j]);
                    wmma::mma_sync(acc[i][j], afl[i], bfh[j], acc[i][j]);
                }
        }
        // next iter writes stage s^1; all readers of s^1 finished before the
        // barrier above (they must pass it to reach this iteration's MMA)
    }

    float* C = Cout + (size_t)ks * M * N;
#pragma unroll
    for (int i = 0; i < 2; i++)
#pragma unroll
        for (int j = 0; j < 2; j++)
            wmma::store_matrix_sync(
                C + (size_t)(m0 + wm * 32 + i * 16) * N + n0 + wn * 32 + j * 16,
                acc[i][j], N, wmma::mem_row_major);
}

// ---------------------------------------------------------------------------
// Gate kernel: reduce KS split-K partials + bias, apply LSTM nonlinearity
// (Keras order i,f,g,o; activation=relu). Writes duplicated [h|h] and/or flat h.
// ---------------------------------------------------------------------------
__global__ void lstm_gate_tc(const float* __restrict__ P, int KS,
                             const float* __restrict__ c_prev,
                             float* __restrict__ c_out,
                             const float* __restrict__ bias,
                             float* __restrict__ hdup, float* __restrict__ hflat) {
    int idx = blockIdx.x * blockDim.x + threadIdx.x;
    if (idx >= Bn * Hn) return;
    int b = idx / Hn;
    int j = idx - b * Hn;
    float zi = bias[j], zf = bias[Hn + j], zg = bias[2 * Hn + j], zo = bias[3 * Hn + j];
    for (int ks = 0; ks < KS; ks++) {
        const float* zr = P + ((size_t)ks * Bn + b) * NG;
        zi += zr[j];
        zf += zr[Hn + j];
        zg += zr[2 * Hn + j];
        zo += zr[3 * Hn + j];
    }
    float ig = 1.f / (1.f + expf(-zi));
    float fg = 1.f / (1.f + expf(-zf));
    float gg = fmaxf(zg, 0.f);
    float og = 1.f / (1.f + expf(-zo));
    float cn = fg * c_prev[idx] + ig * gg;
    c_out[idx] = cn;
    float h = og * fmaxf(cn, 0.f);
    if (hdup) {
        hdup[(size_t)b * 2 * Hn + j] = h;
        hdup[(size_t)b * 2 * Hn + Hn + j] = h;
    }
    if (hflat) hflat[idx] = h;
}

// ---------------------------------------------------------------------------
// Softmax in place on (Bn x Vn), one block per row; adds bias bd to the logits.
// ---------------------------------------------------------------------------
__global__ __launch_bounds__(512)
void softmax_bias(float* __restrict__ probs, const float* __restrict__ bd) {
    const int b = blockIdx.x;
    float* row = probs + (size_t)b * Vn;
    const int tid = threadIdx.x;
    const int nt = blockDim.x;
    __shared__ float sred[33];

    float m = -3.4e38f;
    for (int i = tid; i < Vn; i += nt) m = fmaxf(m, row[i] + bd[i]);
#pragma unroll
    for (int o = 16; o > 0; o >>= 1) m = fmaxf(m, __shfl_xor_sync(0xffffffffu, m, o));
    if ((tid & 31) == 0) sred[tid >> 5] = m;
    __syncthreads();
    if (tid == 0) {
        float v = sred[0];
        for (int w = 1; w < nt / 32; w++) v = fmaxf(v, sred[w]);
        sred[32] = v;
    }
    __syncthreads();
    m = sred[32];

    float s = 0.f;
    for (int i = tid; i < Vn; i += nt) {
        float e = expf(row[i] + bd[i] - m);
        row[i] = e;
        s += e;
    }
    __syncthreads();
#pragma unroll
    for (int o = 16; o > 0; o >>= 1) s += __shfl_xor_sync(0xffffffffu, s, o);
    if ((tid & 31) == 0) sred[tid >> 5] = s;
    __syncthreads();
    if (tid == 0) {
        float v = 0.f;
        for (int w = 0; w < nt / 32; w++) v += sred[w];
        sred[32] = v;
    }
    __syncthreads();
    float inv = 1.f / sred[32];
    for (int i = tid; i < Vn; i += nt) row[i] *= inv;
}

__global__ void copy_tail(const float* __restrict__ h4, const float* __restrict__ c4,
                          float* __restrict__ out) {
    int i = blockIdx.x * blockDim.x + threadIdx.x;
    if (i >= Bn * Hn) return;
    out[(size_t)Bn * Vn + i] = h4[i];
    out[(size_t)Bn * Vn + (size_t)Bn * Hn + i] = c4[i];
}

// ---------------------------------------------------------------------------
// Launch
// ---------------------------------------------------------------------------
extern "C" void kernel_launch(void* const* d_in, const int* in_sizes, int n_in,
                              void* d_out, int out_size) {
    const float* enc = (const float*)d_in[0];
    const float* we  = (const float*)d_in[1];
    const float* h0  = (const float*)d_in[2];
    const float* c0  = (const float*)d_in[3];
    const int*   spk = (const int*)d_in[4];
    // d_in[5] = addressee (unused)
    const float* pe  = (const float*)d_in[6];
    const float* W1 = (const float*)d_in[7];
    const float* U1 = (const float*)d_in[8];
    const float* b1 = (const float*)d_in[9];
    const float* W2 = (const float*)d_in[10];
    const float* U2 = (const float*)d_in[11];
    const float* b2 = (const float*)d_in[12];
    const float* W3 = (const float*)d_in[13];
    const float* U3 = (const float*)d_in[14];
    const float* b3 = (const float*)d_in[15];
    const float* W4 = (const float*)d_in[16];
    const float* U4 = (const float*)d_in[17];
    const float* b4 = (const float*)d_in[18];
    const float* Wd = (const float*)d_in[19];
    const float* bd = (const float*)d_in[20];
    float* out = (float*)d_out;

    float *xp, *pp, *hd, *h4, *cp;
    cudaGetSymbolAddress((void**)&xp, g_x);
    cudaGetSymbolAddress((void**)&pp, g_part);
    cudaGetSymbolAddress((void**)&hd, g_hdup);
    cudaGetSymbolAddress((void**)&h4, g_h4);
    cudaGetSymbolAddress((void**)&cp, g_c);

    cudaFuncSetAttribute(gemm_bf3<0>, cudaFuncAttributeMaxDynamicSharedMemorySize,
                         GEMM_SMEM_BYTES);
    cudaFuncSetAttribute(gemm_bf3<1>, cudaFuncAttributeMaxDynamicSharedMemorySize,
                         GEMM_SMEM_BYTES);

    // 1. Build concatenated input
    build_x<<<(Bn * K1 + 255) / 256, 256>>>(enc, we, h0, spk, pe);

    // 2. Layer 1: z = [x|h0] @ [W1;U1]  (K=11776, split at 11264, KS=8)
    gemm_bf3<1><<<dim3(NG / 64, Bn / 128, 8), 256, GEMM_SMEM_BYTES>>>(
        xp, W1, U1, pp, Bn, NG, K1, DIN1, K1 / 8);
    lstm_gate_tc<<<(Bn * Hn + 255) / 256, 256>>>(pp, 8, c0, cp, b1, hd, nullptr);

    // 3. Layers 2-4: z = [h|h] @ [W;U]  (K=1024, split at 512, KS=4)
    gemm_bf3<1><<<dim3(NG / 64, Bn / 128, 4), 256, GEMM_SMEM_BYTES>>>(
        hd, W2, U2, pp, Bn, NG, 2 * Hn, Hn, 2 * Hn / 4);
    lstm_gate_tc<<<(Bn * Hn + 255) / 256, 256>>>(pp, 4, cp, cp, b2, hd, nullptr);

    gemm_bf3<1><<<dim3(NG / 64, Bn / 128, 4), 256, GEMM_SMEM_BYTES>>>(
        hd, W3, U3, pp, Bn, NG, 2 * Hn, Hn, 2 * Hn / 4);
    lstm_gate_tc<<<(Bn * Hn + 255) / 256, 256>>>(pp, 4, cp, cp, b3, hd, nullptr);

    gemm_bf3<1><<<dim3(NG / 64, Bn / 128, 4), 256, GEMM_SMEM_BYTES>>>(
        hd, W4, U4, pp, Bn, NG, 2 * Hn, Hn, 2 * Hn / 4);
    lstm_gate_tc<<<(Bn * Hn + 255) / 256, 256>>>(pp, 4, cp, cp, b4, nullptr, h4);

    // 4. Decode: logits = h4 @ Wd (bias folded into softmax), softmax in place
    gemm_bf3<0><<<dim3(Vn / 64, Bn / 128, 1), 256, GEMM_SMEM_BYTES>>>(
        h4, Wd, nullptr, out, Bn, Vn, Hn, 0, Hn);
    softmax_bias<<<Bn, 512>>>(out, bd);

    // 5. Append h4, c4
    if (out_size >= Bn * Vn + 2 * Bn * Hn) {
        copy_tail<<<(Bn * Hn + 255) / 256, 256>>>(h4, cp, out);
    }
}